// round 16
// baseline (speedup 1.0000x reference)
#include <cuda_runtime.h>
#include <cuda_fp16.h>
#include <cstdint>
#include <math.h>

#define BB 32
#define SS 4096
#define HH 512
#define UU 512

// Scratch (device globals — no allocations allowed)
__device__ float  g_qproj[BB * UU];
__device__ float  g_scores[BB * SS];        // holds e = exp(score + bva)
__device__ __half g_W2Th[UU * HH];          // [u][h], fp16
__device__ float  g_ctx_part[BB * 64 * HH]; // per-(batch,chunk64) partial contexts
__device__ float  g_esum[BB * 64];          // per-chunk sums of e

// ---------------------------------------------------------------------------
// helpers
// ---------------------------------------------------------------------------
__device__ __forceinline__ uint32_t smem_u32(const void* p) {
    uint32_t a;
    asm("{ .reg .u64 t; cvta.to.shared.u64 t, %1; cvt.u32.u64 %0, t; }" : "=r"(a) : "l"(p));
    return a;
}
__device__ __forceinline__ uint32_t packh2(float a, float b) {
    __half2 h = __floats2half2_rn(a, b);
    return *reinterpret_cast<uint32_t*>(&h);
}
__device__ __forceinline__ float tanh_ap(float x) {
    float y;
    asm("tanh.approx.f32 %0, %1;" : "=f"(y) : "f"(x));
    return y;
}
__device__ __forceinline__ void mma_f16(float (&c)[4], const uint32_t (&a)[4],
                                        const uint32_t (&b)[2]) {
    asm volatile(
        "mma.sync.aligned.m16n8k16.row.col.f32.f16.f16.f32 "
        "{%0,%1,%2,%3}, {%4,%5,%6,%7}, {%8,%9}, {%0,%1,%2,%3};"
        : "+f"(c[0]), "+f"(c[1]), "+f"(c[2]), "+f"(c[3])
        : "r"(a[0]), "r"(a[1]), "r"(a[2]), "r"(a[3]), "r"(b[0]), "r"(b[1]));
}
__device__ __forceinline__ void ldsm4(uint32_t& r0, uint32_t& r1, uint32_t& r2,
                                      uint32_t& r3, uint32_t addr) {
    asm volatile("ldmatrix.sync.aligned.m8n8.x4.shared.b16 {%0,%1,%2,%3}, [%4];"
                 : "=r"(r0), "=r"(r1), "=r"(r2), "=r"(r3) : "r"(addr));
}
__device__ __forceinline__ void cpa16(uint32_t s, const void* g) {
    asm volatile("cp.async.cg.shared.global [%0], [%1], 16;" :: "r"(s), "l"(g));
}

// ---------------------------------------------------------------------------
// Kernel 1: fused prep.
// Blocks 0..255 : W2 -> g_W2Th transpose (32x32 tile).
// Blocks 256..287 : qproj slice uc=(bx-256): u in [uc*16, uc*16+16).
//   512 threads = 16 u-lanes x 32 h-groups (16 h each).  Each thread loads its
//   16 W1 values ONCE into regs, then loops over all 32 batches.  W1 is read
//   once chip-wide (1 MB total vs 32 MB before).
// ---------------------------------------------------------------------------
__global__ __launch_bounds__(512)
void prep_kernel(const float* __restrict__ query,
                 const float* __restrict__ W1,
                 const float* __restrict__ b1,
                 const float* __restrict__ W2,
                 const float* __restrict__ b2) {
    if (blockIdx.x < 256) {
        __shared__ float t[32][33];
        const int bx = (blockIdx.x & 15) * 32, by = (blockIdx.x >> 4) * 32;
        const int x = threadIdx.x & 31, y = threadIdx.x >> 5;  // 32 x 16
#pragma unroll
        for (int j = 0; j < 32; j += 16)
            t[y + j][x] = W2[(size_t)(by + y + j) * UU + bx + x];
        __syncthreads();
#pragma unroll
        for (int j = 0; j < 32; j += 16)
            g_W2Th[(size_t)(bx + y + j) * HH + by + x] = __float2half_rn(t[x][y + j]);
    } else {
        __shared__ float qs[BB * HH / 8];      // staged per 4-batch group: 4*512
        __shared__ float red[32][16];
        const int uc = blockIdx.x - 256;       // 0..31
        const int ul = threadIdx.x & 15;       // u-lane 0..15
        const int hg = threadIdx.x >> 4;       // h-group 0..31
        const int u = uc * 16 + ul;

        // load this thread's 16 W1 values once (coalesced across u-lanes)
        float w[16];
        const float* Wp = W1 + (size_t)(hg * 16) * UU + u;
#pragma unroll
        for (int h = 0; h < 16; ++h) w[h] = Wp[(size_t)h * UU];

        const float bias = b1[u] + b2[u];

        for (int bg = 0; bg < 8; ++bg) {       // 4 batches per group
            // stage 4 batches of query into smem
            for (int i = threadIdx.x; i < 4 * HH; i += 512)
                qs[i] = query[bg * 4 * HH + i];
            __syncthreads();
#pragma unroll
            for (int bb = 0; bb < 4; ++bb) {
                const float* qh = qs + bb * HH + hg * 16;
                float acc = 0.f;
#pragma unroll
                for (int h = 0; h < 16; ++h) acc += qh[h] * w[h];
                red[hg][ul] = acc;
                __syncthreads();
                if (threadIdx.x < 16) {
                    float s = 0.f;
#pragma unroll
                    for (int g2 = 0; g2 < 32; ++g2) s += red[g2][threadIdx.x];
                    g_qproj[(bg * 4 + bb) * UU + uc * 16 + threadIdx.x] = s + bias;
                }
                __syncthreads();
            }
        }
    }
}

// ---------------------------------------------------------------------------
// Kernel 2: fused scores + exp + partial context.  M-tile 64, 2 CTAs/SM.
// fp16 mma m16n8k16 + ldmatrix + cp.async; K-chunk 64; 3 stages; 32 iters.
// 256 threads = 8 warps as 2(M) x 4(N); warp tile 32x32.  (R13 engine, frozen)
// ---------------------------------------------------------------------------
#define ROWB 144
#define A_HALF 9216                    // 64*144
#define B_HALF 18432                   // 128*144
#define STG 27648                      // A_HALF + B_HALF
#define OFF_QP  82944                  // 3*STG
#define OFF_VA  (OFF_QP + 2048)
#define OFF_PART (OFF_VA + 2048)       // 4*64 floats (pad to 2048B)
#define OFF_SC  (OFF_PART + 2048)      // 64 floats (pad 512B)
#define OFF_CTX (OFF_SC + 512)         // 2 sgroups x 512 floats
#define SMEM_SC (OFF_CTX + 4096)       // 93696

__global__ __launch_bounds__(256, 2)
void scores_kernel(const float* __restrict__ values,
                   const float* __restrict__ va,
                   const float* __restrict__ bva) {
    extern __shared__ char smem[];
    const uint32_t sb = smem_u32(smem);
    const int tid = threadIdx.x, lane = tid & 31, wid = tid >> 5;
    const int wm = wid & 1, wn = wid >> 1;          // 2(M) x 4(N) warps
    const int row0 = blockIdx.x * 64;
    const int b = row0 >> 12;
    float* qp_s = (float*)(smem + OFF_QP);
    float* va_s = (float*)(smem + OFF_VA);
    float* part = (float*)(smem + OFF_PART);
    float* sc   = (float*)(smem + OFF_SC);

    for (int i = tid; i < UU; i += 256) {
        qp_s[i] = g_qproj[b * UU + i];
        va_s[i] = va[i];
    }

    const float* Ag = values + (size_t)row0 * HH;
    float4 ra[4];

    auto ldA = [&](int kc) {
#pragma unroll
        for (int i = 0; i < 2; ++i) {
            int idx = tid + i * 256;
            int r = idx >> 3, c = idx & 7;
            const float* p = Ag + (size_t)r * HH + kc * 64 + c * 8;
            ra[2 * i]     = *(const float4*)p;
            ra[2 * i + 1] = *(const float4*)(p + 4);
        }
    };
    auto stA = [&](int st) {
#pragma unroll
        for (int i = 0; i < 2; ++i) {
            int idx = tid + i * 256;
            int r = idx >> 3, c = idx & 7;
            uint4 t;
            t.x = packh2(ra[2 * i].x, ra[2 * i].y);
            t.y = packh2(ra[2 * i].z, ra[2 * i].w);
            t.z = packh2(ra[2 * i + 1].x, ra[2 * i + 1].y);
            t.w = packh2(ra[2 * i + 1].z, ra[2 * i + 1].w);
            *(uint4*)(smem + st * STG + r * ROWB + c * 16) = t;
        }
    };
    auto cpB = [&](int it2, int st) {
        const int nb = it2 >> 3, kc = it2 & 7;
        const __half* Bg = g_W2Th + (size_t)(nb * 128) * HH + kc * 64;
        const uint32_t base = sb + st * STG + A_HALF;
#pragma unroll
        for (int i = 0; i < 4; ++i) {
            int idx = tid + i * 256;
            int r = idx >> 3, c = idx & 7;
            cpa16(base + r * ROWB + c * 16, Bg + (size_t)r * HH + c * 8);
        }
    };

    // ---- prologue ----
    ldA(0); stA(0);
    cpB(0, 0);
    asm volatile("cp.async.commit_group;" ::: "memory");
    ldA(1);

    float acc[2][4][4];
#pragma unroll
    for (int mt = 0; mt < 2; ++mt)
#pragma unroll
        for (int j = 0; j < 4; ++j)
#pragma unroll
            for (int c = 0; c < 4; ++c) acc[mt][j][c] = 0.f;
    float rs[2][2] = {{0.f, 0.f}, {0.f, 0.f}};

    const int g = lane >> 3, l8 = lane & 7;
    const uint32_t a_lm = sb + (uint32_t)((wm * 32 + (g & 1) * 8 + l8) * ROWB + (g >> 1) * 16);
    const uint32_t b_lm = sb + A_HALF +
                          (uint32_t)((wn * 32 + (g >> 1) * 8 + l8) * ROWB + (g & 1) * 16);

    for (int it = 0; it < 32; ++it) {
        const int st = it % 3;
        if (it < 31) {
            const int nst = (it + 1) % 3;
            stA(nst);
            cpB(it + 1, nst);
            if (it < 30) ldA((it + 2) & 7);
            asm volatile("cp.async.commit_group;" ::: "memory");
            asm volatile("cp.async.wait_group 1;" ::: "memory");
        } else {
            asm volatile("cp.async.wait_group 0;" ::: "memory");
        }
        __syncthreads();

        const uint32_t abase = a_lm + st * STG;
        const uint32_t bbase = b_lm + st * STG;
#pragma unroll
        for (int kk = 0; kk < 4; ++kk) {
            uint32_t af[2][4];
            ldsm4(af[0][0], af[0][1], af[0][2], af[0][3], abase + kk * 32);
            ldsm4(af[1][0], af[1][1], af[1][2], af[1][3], abase + 2304 + kk * 32);
            uint32_t bf[4][2];
            ldsm4(bf[0][0], bf[0][1], bf[1][0], bf[1][1], bbase + kk * 32);
            ldsm4(bf[2][0], bf[2][1], bf[3][0], bf[3][1], bbase + 2304 + kk * 32);
#pragma unroll
            for (int mt = 0; mt < 2; ++mt)
#pragma unroll
                for (int j = 0; j < 4; ++j)
                    mma_f16(acc[mt][j], af[mt], bf[j]);
        }

        if ((it & 7) == 7) {                   // end of N-chunk: tanh + va-dot
            const int nb = it >> 3;
#pragma unroll
            for (int mt = 0; mt < 2; ++mt)
#pragma unroll
                for (int j = 0; j < 4; ++j) {
                    int u0 = nb * 128 + wn * 32 + j * 8 + (lane & 3) * 2;
                    float q0 = qp_s[u0], q1 = qp_s[u0 + 1];
                    float v0 = va_s[u0], v1 = va_s[u0 + 1];
                    rs[mt][0] += tanh_ap(acc[mt][j][0] + q0) * v0 + tanh_ap(acc[mt][j][1] + q1) * v1;
                    rs[mt][1] += tanh_ap(acc[mt][j][2] + q0) * v0 + tanh_ap(acc[mt][j][3] + q1) * v1;
                    acc[mt][j][0] = 0.f; acc[mt][j][1] = 0.f;
                    acc[mt][j][2] = 0.f; acc[mt][j][3] = 0.f;
                }
        }
    }

    // ---- single cross-warp reduction ----
#pragma unroll
    for (int off = 1; off <= 2; off <<= 1) {
#pragma unroll
        for (int mt = 0; mt < 2; ++mt) {
            rs[mt][0] += __shfl_xor_sync(0xffffffffu, rs[mt][0], off);
            rs[mt][1] += __shfl_xor_sync(0xffffffffu, rs[mt][1], off);
        }
    }
    if ((lane & 3) == 0) {
        int lr = lane >> 2;
        part[wn * 64 + wm * 32 + lr]      = rs[0][0];
        part[wn * 64 + wm * 32 + lr + 8]  = rs[0][1];
        part[wn * 64 + wm * 32 + lr + 16] = rs[1][0];
        part[wn * 64 + wm * 32 + lr + 24] = rs[1][1];
    }
    __syncthreads();

    // ---- tail 1: e = exp(score + bva) ----
    if (tid < 64) {
        float s = part[tid] + part[64 + tid] + part[128 + tid] + part[192 + tid];
        float e = __expf(s + bva[0]);
        sc[tid] = e;
        g_scores[row0 + tid] = e;
    }
    __syncthreads();

    // per-chunk e-sum (deterministic fixed tree)
    if (tid < 32) {
        float e2 = sc[tid] + sc[tid + 32];
#pragma unroll
        for (int off = 16; off > 0; off >>= 1)
            e2 += __shfl_xor_sync(0xffffffffu, e2, off);
        if (tid == 0) g_esum[blockIdx.x] = e2;
    }

    // ---- tail 2: partial context ----
    {
        const int sg = tid >> 7;       // 0..1 row-group
        const int hq = tid & 127;      // h-quad
        const float* vb = values + (size_t)row0 * HH + hq * 4;
        float ax = 0.f, ay = 0.f, az = 0.f, aw = 0.f;
#pragma unroll 8
        for (int r = sg; r < 64; r += 2) {
            float e = sc[r];
            float4 v = *(const float4*)(vb + (size_t)r * HH);
            ax += e * v.x; ay += e * v.y; az += e * v.z; aw += e * v.w;
        }
        float4* cx = (float4*)(smem + OFF_CTX);
        cx[sg * 128 + hq] = make_float4(ax, ay, az, aw);
    }
    __syncthreads();
    {
        const float* cxf = (float*)(smem + OFF_CTX);
        float* dst = g_ctx_part + (size_t)blockIdx.x * HH;
        dst[tid]       = cxf[tid] + cxf[512 + tid];
        dst[tid + 256] = cxf[256 + tid] + cxf[768 + tid];
    }
}

// ---------------------------------------------------------------------------
// Kernel 3: finalize (frozen). grid (9, 32) x 512.
// ---------------------------------------------------------------------------
__global__ __launch_bounds__(512)
void finalize_kernel(float* __restrict__ out) {
    const int b = blockIdx.y;
    const int bx = blockIdx.x;
    const int tid = threadIdx.x;

    __shared__ float s[64];
    __shared__ float invZ_s;
    if (tid < 64) s[tid] = g_esum[b * 64 + tid];
    __syncthreads();
    if (tid < 32) {
        float v = s[tid] + s[tid + 32];
#pragma unroll
        for (int off = 16; off > 0; off >>= 1)
            v += __shfl_xor_sync(0xffffffffu, v, off);
        if (tid == 0) invZ_s = 1.f / v;
    }
    __syncthreads();
    const float invZ = invZ_s;

    if (bx < 8) {
        const int i = bx * 512 + tid;
        out[b * SS + i] = g_scores[b * SS + i] * invZ;
    } else {
        const float* p = g_ctx_part + (size_t)(b * 64) * HH + tid;
        float acc = 0.f;
#pragma unroll
        for (int c = 0; c < 64; ++c) acc += p[(size_t)c * HH];
        out[BB * SS + b * HH + tid] = acc * invZ;
    }
}

// ---------------------------------------------------------------------------
// Launch
// ---------------------------------------------------------------------------
extern "C" void kernel_launch(void* const* d_in, const int* in_sizes, int n_in,
                              void* d_out, int out_size) {
    const float* query  = (const float*)d_in[0];
    const float* values = (const float*)d_in[1];
    const float* W1     = (const float*)d_in[2];
    const float* b1     = (const float*)d_in[3];
    const float* W2     = (const float*)d_in[4];
    const float* b2     = (const float*)d_in[5];
    const float* va     = (const float*)d_in[6];
    const float* bva    = (const float*)d_in[7];
    float* out = (float*)d_out;

    cudaFuncSetAttribute(scores_kernel, cudaFuncAttributeMaxDynamicSharedMemorySize,
                         SMEM_SC);

    prep_kernel<<<288, 512>>>(query, W1, b1, W2, b2);
    scores_kernel<<<(BB * SS) / 64, 256, SMEM_SC>>>(values, va, bva);
    finalize_kernel<<<dim3(9, BB), 512>>>(out);
}

// round 17
// speedup vs baseline: 1.0710x; 1.0710x over previous
#include <cuda_runtime.h>
#include <cuda_fp16.h>
#include <cstdint>
#include <math.h>

#define BB 32
#define SS 4096
#define HH 512
#define UU 512

// Scratch (device globals — no allocations allowed)
__device__ float  g_qproj[BB * UU];
__device__ float  g_scores[BB * SS];        // holds e = exp(score + bva)
__device__ __half g_W2Th[UU * HH];          // [u][h], fp16
__device__ float  g_ctx_part[BB * 64 * HH]; // per-(batch,chunk64) partial contexts
__device__ float  g_esum[BB * 64];          // per-chunk sums of e

// ---------------------------------------------------------------------------
// helpers
// ---------------------------------------------------------------------------
__device__ __forceinline__ uint32_t smem_u32(const void* p) {
    uint32_t a;
    asm("{ .reg .u64 t; cvta.to.shared.u64 t, %1; cvt.u32.u64 %0, t; }" : "=r"(a) : "l"(p));
    return a;
}
__device__ __forceinline__ uint32_t packh2(float a, float b) {
    __half2 h = __floats2half2_rn(a, b);
    return *reinterpret_cast<uint32_t*>(&h);
}
__device__ __forceinline__ float tanh_ap(float x) {
    float y;
    asm("tanh.approx.f32 %0, %1;" : "=f"(y) : "f"(x));
    return y;
}
__device__ __forceinline__ void mma_f16(float (&c)[4], const uint32_t (&a)[4],
                                        const uint32_t (&b)[2]) {
    asm volatile(
        "mma.sync.aligned.m16n8k16.row.col.f32.f16.f16.f32 "
        "{%0,%1,%2,%3}, {%4,%5,%6,%7}, {%8,%9}, {%0,%1,%2,%3};"
        : "+f"(c[0]), "+f"(c[1]), "+f"(c[2]), "+f"(c[3])
        : "r"(a[0]), "r"(a[1]), "r"(a[2]), "r"(a[3]), "r"(b[0]), "r"(b[1]));
}
__device__ __forceinline__ void ldsm4(uint32_t& r0, uint32_t& r1, uint32_t& r2,
                                      uint32_t& r3, uint32_t addr) {
    asm volatile("ldmatrix.sync.aligned.m8n8.x4.shared.b16 {%0,%1,%2,%3}, [%4];"
                 : "=r"(r0), "=r"(r1), "=r"(r2), "=r"(r3) : "r"(addr));
}
__device__ __forceinline__ void cpa16(uint32_t s, const void* g) {
    asm volatile("cp.async.cg.shared.global [%0], [%1], 16;" :: "r"(s), "l"(g));
}

// ---------------------------------------------------------------------------
// Kernel 1: fused prep.
// Blocks 0..255   : W2 -> g_W2Th transpose (32x32 tile).
// Blocks 256..511 : qproj, block q=(bx-256): bp=q>>4 (batch PAIR), uc=q&15.
//   512 threads = 32 u-lanes x 16 h-groups; each thread sums 32 h's for TWO
//   batches sharing each loaded W1 value; fixed-order 16-way reduction per
//   (batch,u).  Per-(b,u) arithmetic identical to the R15 layout.
// ---------------------------------------------------------------------------
__global__ __launch_bounds__(512)
void prep_kernel(const float* __restrict__ query,
                 const float* __restrict__ W1,
                 const float* __restrict__ b1,
                 const float* __restrict__ W2,
                 const float* __restrict__ b2) {
    if (blockIdx.x < 256) {
        __shared__ float t[32][33];
        const int bx = (blockIdx.x & 15) * 32, by = (blockIdx.x >> 4) * 32;
        const int x = threadIdx.x & 31, y = threadIdx.x >> 5;  // 32 x 16
#pragma unroll
        for (int j = 0; j < 32; j += 16)
            t[y + j][x] = W2[(size_t)(by + y + j) * UU + bx + x];
        __syncthreads();
#pragma unroll
        for (int j = 0; j < 32; j += 16)
            g_W2Th[(size_t)(bx + y + j) * HH + by + x] = __float2half_rn(t[x][y + j]);
    } else {
        __shared__ float qs2[2][HH];
        __shared__ float red2[2][16][32];
        const int q = blockIdx.x - 256;       // 0..255
        const int bp = q >> 4, uc = q & 15;   // batch pair, u-chunk
        const int ul = threadIdx.x & 31;      // u-lane 0..31
        const int hg = threadIdx.x >> 5;      // h-group 0..15
        const int u = uc * 32 + ul;
        qs2[0][threadIdx.x] = query[(2 * bp) * HH + threadIdx.x];
        qs2[1][threadIdx.x] = query[(2 * bp + 1) * HH + threadIdx.x];
        __syncthreads();
        const float* Wp = W1 + (size_t)(hg * 32) * UU + u;
        const float* q0 = qs2[0] + hg * 32;
        const float* q1 = qs2[1] + hg * 32;
        float a0 = 0.f, a1 = 0.f;
#pragma unroll
        for (int h = 0; h < 32; ++h) {
            float w = Wp[(size_t)h * UU];
            a0 += q0[h] * w;
            a1 += q1[h] * w;
        }
        red2[0][hg][ul] = a0;
        red2[1][hg][ul] = a1;
        __syncthreads();
        if (threadIdx.x < 64) {
            const int bb = threadIdx.x >> 5;      // 0..1
            const int uu = uc * 32 + (threadIdx.x & 31);
            float s = 0.f;
#pragma unroll
            for (int g2 = 0; g2 < 16; ++g2) s += red2[bb][g2][threadIdx.x & 31];
            g_qproj[(2 * bp + bb) * UU + uu] = s + b1[uu] + b2[uu];
        }
    }
}

// ---------------------------------------------------------------------------
// Kernel 2: fused scores + exp + partial context.  M-tile 64, 2 CTAs/SM.
// fp16 mma m16n8k16 + ldmatrix + cp.async; K-chunk 64; 3 stages; 32 iters.
// 256 threads = 8 warps as 2(M) x 4(N); warp tile 32x32.  (R13 engine, frozen)
// ---------------------------------------------------------------------------
#define ROWB 144
#define A_HALF 9216                    // 64*144
#define B_HALF 18432                   // 128*144
#define STG 27648                      // A_HALF + B_HALF
#define OFF_QP  82944                  // 3*STG
#define OFF_VA  (OFF_QP + 2048)
#define OFF_PART (OFF_VA + 2048)       // 4*64 floats (pad to 2048B)
#define OFF_SC  (OFF_PART + 2048)      // 64 floats (pad 512B)
#define OFF_CTX (OFF_SC + 512)         // 2 sgroups x 512 floats
#define SMEM_SC (OFF_CTX + 4096)       // 93696

__global__ __launch_bounds__(256, 2)
void scores_kernel(const float* __restrict__ values,
                   const float* __restrict__ va,
                   const float* __restrict__ bva) {
    extern __shared__ char smem[];
    const uint32_t sb = smem_u32(smem);
    const int tid = threadIdx.x, lane = tid & 31, wid = tid >> 5;
    const int wm = wid & 1, wn = wid >> 1;          // 2(M) x 4(N) warps
    const int row0 = blockIdx.x * 64;
    const int b = row0 >> 12;
    float* qp_s = (float*)(smem + OFF_QP);
    float* va_s = (float*)(smem + OFF_VA);
    float* part = (float*)(smem + OFF_PART);
    float* sc   = (float*)(smem + OFF_SC);

    for (int i = tid; i < UU; i += 256) {
        qp_s[i] = g_qproj[b * UU + i];
        va_s[i] = va[i];
    }

    const float* Ag = values + (size_t)row0 * HH;
    float4 ra[4];

    auto ldA = [&](int kc) {
#pragma unroll
        for (int i = 0; i < 2; ++i) {
            int idx = tid + i * 256;
            int r = idx >> 3, c = idx & 7;
            const float* p = Ag + (size_t)r * HH + kc * 64 + c * 8;
            ra[2 * i]     = *(const float4*)p;
            ra[2 * i + 1] = *(const float4*)(p + 4);
        }
    };
    auto stA = [&](int st) {
#pragma unroll
        for (int i = 0; i < 2; ++i) {
            int idx = tid + i * 256;
            int r = idx >> 3, c = idx & 7;
            uint4 t;
            t.x = packh2(ra[2 * i].x, ra[2 * i].y);
            t.y = packh2(ra[2 * i].z, ra[2 * i].w);
            t.z = packh2(ra[2 * i + 1].x, ra[2 * i + 1].y);
            t.w = packh2(ra[2 * i + 1].z, ra[2 * i + 1].w);
            *(uint4*)(smem + st * STG + r * ROWB + c * 16) = t;
        }
    };
    auto cpB = [&](int it2, int st) {
        const int nb = it2 >> 3, kc = it2 & 7;
        const __half* Bg = g_W2Th + (size_t)(nb * 128) * HH + kc * 64;
        const uint32_t base = sb + st * STG + A_HALF;
#pragma unroll
        for (int i = 0; i < 4; ++i) {
            int idx = tid + i * 256;
            int r = idx >> 3, c = idx & 7;
            cpa16(base + r * ROWB + c * 16, Bg + (size_t)r * HH + c * 8);
        }
    };

    // ---- prologue ----
    ldA(0); stA(0);
    cpB(0, 0);
    asm volatile("cp.async.commit_group;" ::: "memory");
    ldA(1);

    float acc[2][4][4];
#pragma unroll
    for (int mt = 0; mt < 2; ++mt)
#pragma unroll
        for (int j = 0; j < 4; ++j)
#pragma unroll
            for (int c = 0; c < 4; ++c) acc[mt][j][c] = 0.f;
    float rs[2][2] = {{0.f, 0.f}, {0.f, 0.f}};

    const int g = lane >> 3, l8 = lane & 7;
    const uint32_t a_lm = sb + (uint32_t)((wm * 32 + (g & 1) * 8 + l8) * ROWB + (g >> 1) * 16);
    const uint32_t b_lm = sb + A_HALF +
                          (uint32_t)((wn * 32 + (g >> 1) * 8 + l8) * ROWB + (g & 1) * 16);

    for (int it = 0; it < 32; ++it) {
        const int st = it % 3;
        if (it < 31) {
            const int nst = (it + 1) % 3;
            stA(nst);
            cpB(it + 1, nst);
            if (it < 30) ldA((it + 2) & 7);
            asm volatile("cp.async.commit_group;" ::: "memory");
            asm volatile("cp.async.wait_group 1;" ::: "memory");
        } else {
            asm volatile("cp.async.wait_group 0;" ::: "memory");
        }
        __syncthreads();

        const uint32_t abase = a_lm + st * STG;
        const uint32_t bbase = b_lm + st * STG;
#pragma unroll
        for (int kk = 0; kk < 4; ++kk) {
            uint32_t af[2][4];
            ldsm4(af[0][0], af[0][1], af[0][2], af[0][3], abase + kk * 32);
            ldsm4(af[1][0], af[1][1], af[1][2], af[1][3], abase + 2304 + kk * 32);
            uint32_t bf[4][2];
            ldsm4(bf[0][0], bf[0][1], bf[1][0], bf[1][1], bbase + kk * 32);
            ldsm4(bf[2][0], bf[2][1], bf[3][0], bf[3][1], bbase + 2304 + kk * 32);
#pragma unroll
            for (int mt = 0; mt < 2; ++mt)
#pragma unroll
                for (int j = 0; j < 4; ++j)
                    mma_f16(acc[mt][j], af[mt], bf[j]);
        }

        if ((it & 7) == 7) {                   // end of N-chunk: tanh + va-dot
            const int nb = it >> 3;
#pragma unroll
            for (int mt = 0; mt < 2; ++mt)
#pragma unroll
                for (int j = 0; j < 4; ++j) {
                    int u0 = nb * 128 + wn * 32 + j * 8 + (lane & 3) * 2;
                    float q0 = qp_s[u0], q1 = qp_s[u0 + 1];
                    float v0 = va_s[u0], v1 = va_s[u0 + 1];
                    rs[mt][0] += tanh_ap(acc[mt][j][0] + q0) * v0 + tanh_ap(acc[mt][j][1] + q1) * v1;
                    rs[mt][1] += tanh_ap(acc[mt][j][2] + q0) * v0 + tanh_ap(acc[mt][j][3] + q1) * v1;
                    acc[mt][j][0] = 0.f; acc[mt][j][1] = 0.f;
                    acc[mt][j][2] = 0.f; acc[mt][j][3] = 0.f;
                }
        }
    }

    // ---- single cross-warp reduction ----
#pragma unroll
    for (int off = 1; off <= 2; off <<= 1) {
#pragma unroll
        for (int mt = 0; mt < 2; ++mt) {
            rs[mt][0] += __shfl_xor_sync(0xffffffffu, rs[mt][0], off);
            rs[mt][1] += __shfl_xor_sync(0xffffffffu, rs[mt][1], off);
        }
    }
    if ((lane & 3) == 0) {
        int lr = lane >> 2;
        part[wn * 64 + wm * 32 + lr]      = rs[0][0];
        part[wn * 64 + wm * 32 + lr + 8]  = rs[0][1];
        part[wn * 64 + wm * 32 + lr + 16] = rs[1][0];
        part[wn * 64 + wm * 32 + lr + 24] = rs[1][1];
    }
    __syncthreads();

    // ---- tail 1: e = exp(score + bva) ----
    if (tid < 64) {
        float s = part[tid] + part[64 + tid] + part[128 + tid] + part[192 + tid];
        float e = __expf(s + bva[0]);
        sc[tid] = e;
        g_scores[row0 + tid] = e;
    }
    __syncthreads();

    // per-chunk e-sum (deterministic fixed tree)
    if (tid < 32) {
        float e2 = sc[tid] + sc[tid + 32];
#pragma unroll
        for (int off = 16; off > 0; off >>= 1)
            e2 += __shfl_xor_sync(0xffffffffu, e2, off);
        if (tid == 0) g_esum[blockIdx.x] = e2;
    }

    // ---- tail 2: partial context ----
    {
        const int sg = tid >> 7;       // 0..1 row-group
        const int hq = tid & 127;      // h-quad
        const float* vb = values + (size_t)row0 * HH + hq * 4;
        float ax = 0.f, ay = 0.f, az = 0.f, aw = 0.f;
#pragma unroll 8
        for (int r = sg; r < 64; r += 2) {
            float e = sc[r];
            float4 v = *(const float4*)(vb + (size_t)r * HH);
            ax += e * v.x; ay += e * v.y; az += e * v.z; aw += e * v.w;
        }
        float4* cx = (float4*)(smem + OFF_CTX);
        cx[sg * 128 + hq] = make_float4(ax, ay, az, aw);
    }
    __syncthreads();
    {
        const float* cxf = (float*)(smem + OFF_CTX);
        float* dst = g_ctx_part + (size_t)blockIdx.x * HH;
        dst[tid]       = cxf[tid] + cxf[512 + tid];
        dst[tid + 256] = cxf[256 + tid] + cxf[768 + tid];
    }
}

// ---------------------------------------------------------------------------
// Kernel 3: finalize (frozen). grid (9, 32) x 512.
// ---------------------------------------------------------------------------
__global__ __launch_bounds__(512)
void finalize_kernel(float* __restrict__ out) {
    const int b = blockIdx.y;
    const int bx = blockIdx.x;
    const int tid = threadIdx.x;

    __shared__ float s[64];
    __shared__ float invZ_s;
    if (tid < 64) s[tid] = g_esum[b * 64 + tid];
    __syncthreads();
    if (tid < 32) {
        float v = s[tid] + s[tid + 32];
#pragma unroll
        for (int off = 16; off > 0; off >>= 1)
            v += __shfl_xor_sync(0xffffffffu, v, off);
        if (tid == 0) invZ_s = 1.f / v;
    }
    __syncthreads();
    const float invZ = invZ_s;

    if (bx < 8) {
        const int i = bx * 512 + tid;
        out[b * SS + i] = g_scores[b * SS + i] * invZ;
    } else {
        const float* p = g_ctx_part + (size_t)(b * 64) * HH + tid;
        float acc = 0.f;
#pragma unroll
        for (int c = 0; c < 64; ++c) acc += p[(size_t)c * HH];
        out[BB * SS + b * HH + tid] = acc * invZ;
    }
}

// ---------------------------------------------------------------------------
// Launch
// ---------------------------------------------------------------------------
extern "C" void kernel_launch(void* const* d_in, const int* in_sizes, int n_in,
                              void* d_out, int out_size) {
    const float* query  = (const float*)d_in[0];
    const float* values = (const float*)d_in[1];
    const float* W1     = (const float*)d_in[2];
    const float* b1     = (const float*)d_in[3];
    const float* W2     = (const float*)d_in[4];
    const float* b2     = (const float*)d_in[5];
    const float* va     = (const float*)d_in[6];
    const float* bva    = (const float*)d_in[7];
    float* out = (float*)d_out;

    cudaFuncSetAttribute(scores_kernel, cudaFuncAttributeMaxDynamicSharedMemorySize,
                         SMEM_SC);

    prep_kernel<<<512, 512>>>(query, W1, b1, W2, b2);
    scores_kernel<<<(BB * SS) / 64, 256, SMEM_SC>>>(values, va, bva);
    finalize_kernel<<<dim3(9, BB), 512>>>(out);
}